// round 13
// baseline (speedup 1.0000x reference)
#include <cuda_runtime.h>

#define BATCH   8192
#define BM      64
#define GRID    128
#define NTHR    512
#define TSTEPS  24
#define HDIM    256
#define NCHUNK  4          // 64 h-cols per chunk
#define NKT     8          // tiles per chunk (8 kpp = 32 k each)
#define TPLANE  257        // u128 stride between kpp planes (pad for staging)
#define TILE_T  (8 * TPLANE)   // u128 per tile = 2056 -> 32896 B

#define OFF_A0    0
#define OFF_A1    65536
#define OFF_W     131072          // 2 * 32896 = 65792 -> ends 196864
#define OFF_BIAS  196864          // 4096
#define OFF_WIH   200960          // 8192
#define OFF_TF    209152          // 6144
#define OFF_TM    215296          // 6144
#define OFF_WLR   221440          // 2048
#define OFF_HDOT  223488          // 256
#define OFF_SDOT  223744          // 256
#define OFF_RED   224000          // 256
#define OFF_FLAG  224256          // 16
#define SMEM_BYTES 224272

__device__ float g_cstate[BATCH * HDIM];
__device__ float g_blockSums[GRID];
__device__ unsigned int g_ctr;

__device__ __forceinline__ void ffma2(unsigned long long& acc,
                                      unsigned long long a,
                                      unsigned long long b) {
    asm volatile("fma.rn.f32x2 %0, %1, %2, %0;" : "+l"(acc) : "l"(a), "l"(b));
}
__device__ __forceinline__ float2 up64(unsigned long long v) {
    float2 r;
    asm("mov.b64 {%0, %1}, %2;" : "=f"(r.x), "=f"(r.y) : "l"(v));
    return r;
}
__device__ __forceinline__ float sigm(float x) { return 1.f / (1.f + __expf(-x)); }
__device__ __forceinline__ float tanh_f(float x) { return 1.f - 2.f / (__expf(2.f * x) + 1.f); }

__device__ __forceinline__ void cp16(void* smem_dst, const void* gsrc) {
    unsigned int d = (unsigned int)__cvta_generic_to_shared(smem_dst);
    asm volatile("cp.async.cg.shared.global [%0], [%1], 16;" :: "r"(d), "l"(gsrc));
}

// Stage one LSTM W tile: 256 wrows (g*64+col) x 8 kpp, u128 = 4 consecutive k-floats.
// dst layout: [kpp][wrow] u128 with plane stride TPLANE.
__device__ __forceinline__ void issue_w_lstm(const float* __restrict__ Whh,
                                             int c, int kt,
                                             ulonglong2* dst, int tid) {
#pragma unroll
    for (int i = 0; i < 4; i++) {
        int lin = i * 512 + tid;          // 0..2047
        int wrow = lin >> 3;              // 0..255 = g*64 + cl
        int kpp  = lin & 7;
        int g = wrow >> 6, cl = wrow & 63;
        const float* src = Whh + (((g << 8) + (c << 6) + cl) << 8) + (kt << 5) + (kpp << 2);
        cp16(dst + kpp * TPLANE + wrow, src);
    }
}

// Stage one MLP W tile: 64 wrows (out-cols of chunk) x 8 kpp.
__device__ __forceinline__ void issue_w_mlp(const float* __restrict__ W,
                                            int c, int kt,
                                            ulonglong2* dst, int tid) {
    int wrow = tid >> 3;                  // 0..63
    int kpp  = tid & 7;
    const float* src = W + (((c << 6) + wrow) << 8) + (kt << 5) + (kpp << 2);
    cp16(dst + kpp * TPLANE + wrow, src);
}

// MLP layer: out[r][n] = relu(in . W[n] + b[n]); 4 chunks of 64 out-cols.
__device__ __forceinline__ void mlp_layer(const float* __restrict__ in,
                                          float* __restrict__ outb,
                                          const float* __restrict__ W,
                                          const float* __restrict__ bias,
                                          ulonglong2* Wbuf,
                                          int tid, int tx, int rg, int wc) {
    const ulonglong2* Au = (const ulonglong2*)in;
    const int rbase = rg << 3;
#pragma unroll 1
    for (int c = 0; c < 4; c++) {
        unsigned long long acc[8];
#pragma unroll
        for (int v = 0; v < 8; v++) acc[v] = 0ull;

        issue_w_mlp(W, c, 0, Wbuf, tid);
        asm volatile("cp.async.commit_group;");
#pragma unroll 1
        for (int kt = 0; kt < 8; kt++) {
            asm volatile("cp.async.wait_group 0;");
            __syncthreads();
            if (kt + 1 < 8) {
                issue_w_mlp(W, c, kt + 1, Wbuf + ((kt + 1) & 1) * TILE_T, tid);
                asm volatile("cp.async.commit_group;");
            }
            const ulonglong2* Wt = Wbuf + (kt & 1) * TILE_T;
#pragma unroll 1
            for (int kpp = 0; kpp < 8; kpp++) {
                ulonglong2 a[8];
#pragma unroll
                for (int v = 0; v < 8; v++) a[v] = Au[(rbase + v) * 64 + (kt << 3) + kpp];
                ulonglong2 b = Wt[kpp * TPLANE + (wc << 5) + tx];
#pragma unroll
                for (int v = 0; v < 8; v++) { ffma2(acc[v], a[v].x, b.x); ffma2(acc[v], a[v].y, b.y); }
            }
            __syncthreads();
        }
        int n = (c << 6) + (wc << 5) + tx;
        float bb = bias[n];
#pragma unroll
        for (int v = 0; v < 8; v++) {
            float2 p = up64(acc[v]);
            outb[(rbase + v) * HDIM + n] = fmaxf(p.x + p.y + bb, 0.f);
        }
        __syncthreads();
    }
}

__device__ __forceinline__ void dot256_512(const float* __restrict__ buf,
                                           const float* __restrict__ w,
                                           float* __restrict__ outv, int tid) {
    int r = tid >> 3, q = tid & 7;        // 8 threads per row, 32 f32 each
    const float4* hv = (const float4*)(buf + r * HDIM + q * 32);
    const float4* wv = (const float4*)(w + q * 32);
    float s = 0.f;
#pragma unroll
    for (int i = 0; i < 8; i++) {
        float4 a = hv[i], b = wv[i];
        s += a.x * b.x + a.y * b.y + a.z * b.z + a.w * b.w;
    }
    s += __shfl_xor_sync(0xffffffffu, s, 1);
    s += __shfl_xor_sync(0xffffffffu, s, 2);
    s += __shfl_xor_sync(0xffffffffu, s, 4);
    if (q == 0) outv[r] = s;
}

__global__ void __launch_bounds__(NTHR, 1)
fused_kernel(const float* __restrict__ statf, const float* __restrict__ tf,
             const float* __restrict__ tm, const float* __restrict__ tgt,
             const float* __restrict__ h0, const float* __restrict__ c0,
             const float* __restrict__ Wih, const float* __restrict__ Whh,
             const float* __restrict__ bih, const float* __restrict__ bhh,
             const float* __restrict__ W1, const float* __restrict__ b1,
             const float* __restrict__ W2, const float* __restrict__ b2p,
             const float* __restrict__ W3, const float* __restrict__ b3,
             const float* __restrict__ Wlr, const float* __restrict__ blr,
             float* __restrict__ out) {
    extern __shared__ __align__(16) char smem[];
    const int tid = threadIdx.x;
    const int tx = tid & 31;
    const int wid = tid >> 5;
    const int rg = wid >> 1;              // row-group 0..7 (8 rows each)
    const int wc = wid & 1;               // column half
    const int r0 = blockIdx.x * BM;
    const int rbase = rg << 3;

    float* A0   = (float*)(smem + OFF_A0);
    float* A1   = (float*)(smem + OFF_A1);
    ulonglong2* Wbuf = (ulonglong2*)(smem + OFF_W);
    float* sBias = (float*)(smem + OFF_BIAS);
    float* sWih  = (float*)(smem + OFF_WIH);
    float* sTF   = (float*)(smem + OFF_TF);
    float* sTM   = (float*)(smem + OFF_TM);
    float* sWlr  = (float*)(smem + OFF_WLR);
    float* sHdot = (float*)(smem + OFF_HDOT);
    float* sSdot = (float*)(smem + OFF_SDOT);
    float* sRed  = (float*)(smem + OFF_RED);
    int*   sFlag = (int*)(smem + OFF_FLAG);

#pragma unroll
    for (int i = 0; i < 2; i++) { int k = tid + i * 512; sBias[k] = bih[k] + bhh[k]; }
#pragma unroll
    for (int i = 0; i < 4; i++) { int k = tid + i * 512; sWih[k] = Wih[k]; }
#pragma unroll
    for (int i = 0; i < 3; i++) { int k = tid + i * 512; sTF[k] = tf[r0 * 24 + k]; sTM[k] = tm[r0 * 24 + k]; }
    if (tid < 512) sWlr[tid] = Wlr[tid];
    {
        float4* dst = (float4*)A0;
        const float4* src = (const float4*)(h0 + (long)r0 * HDIM);
#pragma unroll
        for (int i = 0; i < 8; i++) dst[tid + i * 512] = src[tid + i * 512];
    }
    __syncthreads();

    float* Acur = A0;
    float* Anext = A1;

    // prime the W-tile ring
    issue_w_lstm(Whh, 0, 0, Wbuf, tid);
    asm volatile("cp.async.commit_group;");

#pragma unroll 1
    for (int t = 0; t < TSTEPS; t++) {
        const ulonglong2* Au = (const ulonglong2*)Acur;
#pragma unroll 1
        for (int c = 0; c < NCHUNK; c++) {          // 64 h-cols per chunk
            unsigned long long acc[8][4];
#pragma unroll
            for (int v = 0; v < 8; v++)
#pragma unroll
                for (int g = 0; g < 4; g++) acc[v][g] = 0ull;

            const int jg = (c << 6) + (wc << 5) + tx;
            float cold[8];
            {
                const float* csrc = (t == 0) ? c0 : g_cstate;
#pragma unroll
                for (int v = 0; v < 8; v++)
                    cold[v] = csrc[(r0 + rbase + v) * HDIM + jg];
            }

#pragma unroll 1
            for (int kt = 0; kt < NKT; kt++) {
                asm volatile("cp.async.wait_group 0;");
                __syncthreads();
                // issue next tile in the global ring (W is h-independent)
                {
                    int nkt = kt + 1, nc = c;
                    if (nkt == NKT) { nkt = 0; nc = c + 1; if (nc == NCHUNK) nc = 0; }
                    bool last = (t == TSTEPS - 1) && (c == NCHUNK - 1) && (kt == NKT - 1);
                    if (!last) {
                        issue_w_lstm(Whh, nc, nkt, Wbuf + ((kt + 1) & 1) * TILE_T, tid);
                        asm volatile("cp.async.commit_group;");
                    }
                }
                const ulonglong2* Wt = Wbuf + (kt & 1) * TILE_T;
#pragma unroll 1
                for (int kpp = 0; kpp < 8; kpp++) {
                    ulonglong2 a[8];
#pragma unroll
                    for (int v = 0; v < 8; v++)
                        a[v] = Au[(rbase + v) * 64 + (kt << 3) + kpp];
                    const ulonglong2* Bp = Wt + kpp * TPLANE + (wc << 5) + tx;
#pragma unroll
                    for (int g = 0; g < 4; g++) {
                        ulonglong2 b = Bp[g << 6];
#pragma unroll
                        for (int v = 0; v < 8; v++) {
                            ffma2(acc[v][g], a[v].x, b.x);
                            ffma2(acc[v][g], a[v].y, b.y);
                        }
                    }
                }
            }
            // gate nonlinearity + state update (col jg, rows rbase..rbase+7)
#pragma unroll
            for (int v = 0; v < 8; v++) {
                int r = rbase + v;
                float xv = sTF[r * 24 + t], mv = sTM[r * 24 + t];
                float gate[4];
#pragma unroll
                for (int g = 0; g < 4; g++) {
                    int row = (g << 8) + jg;
                    float2 p = up64(acc[v][g]);
                    gate[g] = p.x + p.y + sBias[row]
                            + xv * sWih[row * 2] + mv * sWih[row * 2 + 1];
                }
                float iv = sigm(gate[0]);
                float fv = sigm(gate[1]);
                float gv = tanh_f(gate[2]);
                float ov = sigm(gate[3]);
                float cn = fv * cold[v] + iv * gv;
                g_cstate[(r0 + r) * HDIM + jg] = cn;
                Anext[r * HDIM + jg] = ov * tanh_f(cn);
            }
        }
        { float* tsw = Acur; Acur = Anext; Anext = tsw; }
    }
    __syncthreads();

    dot256_512(Acur, sWlr, sHdot, tid);
    __syncthreads();

    {
        float4* dst = (float4*)Acur;
        const float4* src = (const float4*)(statf + (long)r0 * HDIM);
#pragma unroll
        for (int i = 0; i < 8; i++) dst[tid + i * 512] = src[tid + i * 512];
    }
    __syncthreads();

    mlp_layer(Acur, Anext, W1, b1, Wbuf, tid, tx, rg, wc);
    mlp_layer(Anext, Acur, W2, b2p, Wbuf, tid, tx, rg, wc);
    mlp_layer(Acur, Anext, W3, b3, Wbuf, tid, tx, rg, wc);

    dot256_512(Anext, sWlr + 256, sSdot, tid);
    __syncthreads();

    if (tid < BM) {
        int r = tid;
        float p = sHdot[r] + sSdot[r] + blr[0];
        out[r0 + r] = p;
        float tg = tgt[r0 + r];
        sRed[r] = fmaxf(p, 0.f) - p * tg + log1pf(expf(-fabsf(p)));
    }
    __syncthreads();
    if (tid < 32) {
        float s = sRed[tid] + sRed[tid + 32];
#pragma unroll
        for (int o = 16; o > 0; o >>= 1) s += __shfl_down_sync(0xffffffffu, s, o);
        if (tid == 0) g_blockSums[blockIdx.x] = s;
    }

    // last-CTA-done: final loss reduction
    __threadfence();
    if (tid == 0) {
        unsigned int n = atomicAdd(&g_ctr, 1u);
        sFlag[0] = (n == GRID - 1) ? 1 : 0;
    }
    __syncthreads();
    if (sFlag[0]) {
        float v = 0.f;
        if (tid < GRID) v = ((volatile float*)g_blockSums)[tid];
        float s = v;
#pragma unroll
        for (int o = 16; o > 0; o >>= 1) s += __shfl_down_sync(0xffffffffu, s, o);
        if ((tid & 31) == 0 && tid < GRID) sRed[tid >> 5] = s;
        __syncthreads();
        if (tid == 0) {
            float tot = sRed[0] + sRed[1] + sRed[2] + sRed[3];
            out[BATCH] = tot * (1.0f / (float)BATCH);
            g_ctr = 0;
        }
    }
}

extern "C" void kernel_launch(void* const* d_in, const int* in_sizes, int n_in,
                              void* d_out, int out_size) {
    cudaFuncSetAttribute(fused_kernel, cudaFuncAttributeMaxDynamicSharedMemorySize, SMEM_BYTES);
    const float* statf = (const float*)d_in[0];
    const float* tf    = (const float*)d_in[1];
    const float* tm    = (const float*)d_in[2];
    const float* tgt   = (const float*)d_in[3];
    const float* h0    = (const float*)d_in[4];
    const float* c0    = (const float*)d_in[5];
    const float* Wih   = (const float*)d_in[6];
    const float* Whh   = (const float*)d_in[7];
    const float* bih   = (const float*)d_in[8];
    const float* bhh   = (const float*)d_in[9];
    const float* W1    = (const float*)d_in[10];
    const float* b1    = (const float*)d_in[11];
    const float* W2    = (const float*)d_in[12];
    const float* b2    = (const float*)d_in[13];
    const float* W3    = (const float*)d_in[14];
    const float* b3    = (const float*)d_in[15];
    const float* Wlr   = (const float*)d_in[16];
    const float* blr   = (const float*)d_in[17];
    float* out = (float*)d_out;

    fused_kernel<<<GRID, NTHR, SMEM_BYTES>>>(statf, tf, tm, tgt, h0, c0,
                                             Wih, Whh, bih, bhh,
                                             W1, b1, W2, b2, W3, b3,
                                             Wlr, blr, out);
}

// round 15
// speedup vs baseline: 2.0139x; 2.0139x over previous
#include <cuda_runtime.h>
#include <cuda_bf16.h>

#define BM 64
#define GRID 128
#define NTHR 512
#define TSTEPS 24

typedef unsigned u32; typedef unsigned long long u64;

#define OFF_A    0          // A frags: [buf2][hl2][32KB] = 131072
#define OFF_B    131072     // B frags: [buf2][hl2][8KB] = 32768 ; MLP tiles alias
#define OFF_BIAS 163840     // 4096 (reordered n=j*4+g)
#define OFF_WIH  167936     // 8192 (reordered)
#define OFF_TF   176128     // 6144
#define OFF_TM   182272     // 6144
#define OFF_WLR  188416     // 2048
#define OFF_HD4  190464     // 64*4 f32 = 1024
#define OFF_SD   191488     // 256
#define OFF_RED  191744     // 64
#define OFF_FLAG 191808     // 16
#define SMEM_BYTES 191824

__device__ float g_cstate[8192 * 256];
__device__ u32 g_bhi[131072];   // W_hh hi fragments: [kt16][nt128][lane32] u64 (as 2xu32)
__device__ u32 g_blo[131072];
__device__ float g_blockSums[GRID];
__device__ u32 g_ctr;

__device__ __forceinline__ u32 smem_u32(const void* p) {
    u32 r; asm("{ .reg .u64 t; cvta.to.shared.u64 t, %1; cvt.u32.u64 %0, t; }" : "=r"(r) : "l"(p)); return r;
}
__device__ __forceinline__ float sigm(float x) { return 1.f / (1.f + __expf(-x)); }
__device__ __forceinline__ float tanh_f(float x) { return 1.f - 2.f / (__expf(2.f * x) + 1.f); }
__device__ __forceinline__ void cp16(void* d, const void* s) {
    asm volatile("cp.async.cg.shared.global [%0], [%1], 16;" :: "r"(smem_u32(d)), "l"(s));
}
__device__ __forceinline__ u32 pk2(float a, float b) {   // round both to bf16, pack
    __nv_bfloat162 t = __floats2bfloat162_rn(a, b); return *(u32*)&t;
}
__device__ __forceinline__ void ffma2(u64& a, u64 x, u64 y) {
    asm volatile("fma.rn.f32x2 %0, %1, %2, %0;" : "+l"(a) : "l"(x), "l"(y));
}
__device__ __forceinline__ float2 up64(u64 v) { float2 r; asm("mov.b64 {%0,%1}, %2;" : "=f"(r.x), "=f"(r.y) : "l"(v)); return r; }

__device__ __forceinline__ void mma16816(float* d, const uint4& a, u64 b) {
    u32 b0 = (u32)b, b1 = (u32)(b >> 32);
    asm volatile("mma.sync.aligned.m16n8k16.row.col.f32.bf16.bf16.f32 "
        "{%0,%1,%2,%3}, {%4,%5,%6,%7}, {%8,%9}, {%0,%1,%2,%3};"
        : "+f"(d[0]), "+f"(d[1]), "+f"(d[2]), "+f"(d[3])
        : "r"(a.x), "r"(a.y), "r"(a.z), "r"(a.w), "r"(b0), "r"(b1));
}

// Split W_hh into bf16 hi/lo HMMA B-fragments.
// Logical B col n = j*4 + gate (gate-interleaved); W row R = gate*256 + j.
// Fragment: tile (kt=k/16, nt=n/8); lane = (n%8)*4 + ((k%16)%8)/2; reg = (k%16)>=8.
__global__ void prep_whh(const float* __restrict__ Whh) {
    int idx = blockIdx.x * 256 + threadIdx.x;     // 131072
    int n = idx >> 7, p = idx & 127, k = p * 2;
    int g = n & 3, j = n >> 2;
    const float* src = Whh + (size_t)((g << 8) + j) * 256 + k;
    float w0 = src[0], w1 = src[1];
    __nv_bfloat16 h0 = __float2bfloat16(w0), h1 = __float2bfloat16(w1);
    int kt = k >> 4, nt = n >> 3;
    int lane = (n & 7) * 4 + ((k & 7) >> 1);
    int reg = ((k & 15) >= 8);
    int pos = ((kt * 128 + nt) * 32 + lane) * 2 + reg;
    __nv_bfloat162 hp; hp.x = h0; hp.y = h1;
    g_bhi[pos] = *(u32*)&hp;
    g_blo[pos] = pk2(w0 - __bfloat162float(h0), w1 - __bfloat162float(h1));
}

// stage B frags for (chunk cc, ktile kt): 32 nt-tiles hi + lo, 8KB each, linear.
__device__ __forceinline__ void stageB(int cc, int kt, int buf, char* sm, int tid) {
    const u32* shi = g_bhi + (kt * 128 + cc * 32) * 64;
    const u32* slo = g_blo + (kt * 128 + cc * 32) * 64;
    char* d = sm + OFF_B + buf * 16384;
    cp16(d + tid * 16, shi + tid * 4);
    cp16(d + 8192 + tid * 16, slo + tid * 4);
    asm volatile("cp.async.commit_group;");
}

// ---- MLP (SIMT f32x2), 64 rows, 512 threads ----
__device__ __forceinline__ void mlp_stage(const float* __restrict__ W, int cc, int kt,
                                          char* sm, int tid, int buf) {
    if (tid < 256) {
        int wr = tid >> 2, kpp = tid & 3;
        cp16(sm + OFF_B + (buf * 260 + kpp * 65 + wr) * 16,
             W + (size_t)(cc * 64 + wr) * 256 + (kt * 4 + kpp) * 4);
    }
    asm volatile("cp.async.commit_group;");
}
__device__ void mlp_layer(const float* in, float* outb, const float* __restrict__ W,
                          const float* __restrict__ bias, char* sm, int tid, int tx, int wid) {
    const ulonglong2* Au = (const ulonglong2*)in;
    const int rb = (wid >> 1) * 8, cl = (wid & 1) * 32 + tx;
#pragma unroll 1
    for (int cc = 0; cc < 4; cc++) {
        u64 acc[8];
#pragma unroll
        for (int v = 0; v < 8; v++) acc[v] = 0ull;
        mlp_stage(W, cc, 0, sm, tid, 0);
#pragma unroll 1
        for (int kt = 0; kt < 16; kt++) {
            asm volatile("cp.async.wait_group 0;");
            __syncthreads();
            if (kt < 15) mlp_stage(W, cc, kt + 1, sm, tid, (kt + 1) & 1);
            const ulonglong2* Tt = (const ulonglong2*)(sm + OFF_B) + (kt & 1) * 260;
#pragma unroll
            for (int kpp = 0; kpp < 4; kpp++) {
                ulonglong2 b = Tt[kpp * 65 + cl];
#pragma unroll
                for (int v = 0; v < 8; v++) {
                    ulonglong2 a = Au[(rb + v) * 64 + kt * 4 + kpp];
                    ffma2(acc[v], a.x, b.x); ffma2(acc[v], a.y, b.y);
                }
            }
        }
        __syncthreads();
        int n = cc * 64 + cl; float bb = bias[n];
#pragma unroll
        for (int v = 0; v < 8; v++) {
            float2 p = up64(acc[v]);
            outb[(rb + v) * 256 + n] = fmaxf(p.x + p.y + bb, 0.f);
        }
        __syncthreads();
    }
}
__device__ __forceinline__ void dot256_512(const float* buf, const float* w, float* outv, int tid) {
    int r = tid >> 3, q = tid & 7;
    const float4* hv = (const float4*)(buf + r * 256 + q * 32);
    const float4* wv = (const float4*)(w + q * 32);
    float s = 0.f;
#pragma unroll
    for (int i = 0; i < 8; i++) {
        float4 a = hv[i], b = wv[i];
        s += a.x * b.x + a.y * b.y + a.z * b.z + a.w * b.w;
    }
    s += __shfl_xor_sync(~0u, s, 1);
    s += __shfl_xor_sync(~0u, s, 2);
    s += __shfl_xor_sync(~0u, s, 4);
    if (q == 0) outv[r] = s;
}

__global__ void __launch_bounds__(NTHR, 1)
fused_kernel(const float* __restrict__ statf, const float* __restrict__ tf,
             const float* __restrict__ tm, const float* __restrict__ tgt,
             const float* __restrict__ h0, const float* __restrict__ c0,
             const float* __restrict__ Wih, const float* __restrict__ Whh,
             const float* __restrict__ bih, const float* __restrict__ bhh,
             const float* __restrict__ W1, const float* __restrict__ b1,
             const float* __restrict__ W2, const float* __restrict__ b2p,
             const float* __restrict__ W3, const float* __restrict__ b3,
             const float* __restrict__ Wlr, const float* __restrict__ blr,
             float* __restrict__ out) {
    extern __shared__ __align__(1024) char sm[];
    const int tid = threadIdx.x, tx = tid & 31, wid = tid >> 5;
    const int rt = wid >> 2, cg = wid & 3, q = tx & 3;
    const int r0 = blockIdx.x * BM;
    const int rowp = rt * 16 + (tx >> 2) + ((q & 1) << 3);   // fixed epilogue row

    float* sBias = (float*)(sm + OFF_BIAS);
    float* sWih = (float*)(sm + OFF_WIH);
    float* sTF = (float*)(sm + OFF_TF);
    float* sTM = (float*)(sm + OFF_TM);
    float* sWlr = (float*)(sm + OFF_WLR);
    float* sHD4 = (float*)(sm + OFF_HD4);
    float* sSD = (float*)(sm + OFF_SD);
    float* sRed = (float*)(sm + OFF_RED);
    int* sFlag = (int*)(sm + OFF_FLAG);

    // stage constants (reordered n = j*4+g)
#pragma unroll
    for (int i = 0; i < 2; i++) {
        int n = tid + i * 512, g = n & 3, j = n >> 2;
        sBias[n] = bih[(g << 8) + j] + bhh[(g << 8) + j];
    }
#pragma unroll
    for (int i = 0; i < 4; i++) {
        int m = tid + i * 512, n = m >> 1, c = m & 1, g = n & 3, j = n >> 2;
        sWih[m] = Wih[(size_t)((g << 8) + j) * 2 + c];
    }
#pragma unroll
    for (int i = 0; i < 3; i++) {
        int k = tid + i * 512;
        sTF[k] = tf[(size_t)r0 * 24 + k];
        sTM[k] = tm[(size_t)r0 * 24 + k];
    }
    if (tid < 512) sWlr[tid] = Wlr[tid];
    // A-frag init from h0 (buf 0)
#pragma unroll
    for (int i = 0; i < 16; i++) {
        int idx = tid + i * 512;                  // 8192
        int r = idx >> 7, p = idx & 127, k = p * 2;
        float2 v = *(const float2*)(h0 + (size_t)(r0 + r) * 256 + k);
        __nv_bfloat16 bx = __float2bfloat16(v.x), by = __float2bfloat16(v.y);
        __nv_bfloat162 hp; hp.x = bx; hp.y = by;
        int rr = r & 15, kk = k & 15;
        int lane = (rr & 7) * 4 + ((kk & 7) >> 1);
        int reg = (rr >= 8) + ((kk >= 8) ? 2 : 0);
        u32 off = OFF_A + (((r >> 4) * 16 + (k >> 4)) * 128 + lane * 4 + reg) * 4;
        *(u32*)(sm + off) = *(u32*)&hp;
        *(u32*)(sm + off + 32768) = pk2(v.x - __bfloat162float(bx), v.y - __bfloat162float(by));
    }
    __syncthreads();

    float hd = 0.f;
#pragma unroll 1
    for (int t = 0; t < TSTEPS; t++) {
        const int ab = t & 1, nb = ab ^ 1;
        const float* csrc = t ? g_cstate : c0;
        const float xv = sTF[rowp * 24 + t], mv = sTM[rowp * 24 + t];
#pragma unroll 1
        for (int cc = 0; cc < 4; cc++) {
            float acc[8][4];
#pragma unroll
            for (int i = 0; i < 8; i++)
#pragma unroll
                for (int d = 0; d < 4; d++) acc[i][d] = 0.f;
            float cold[8];
#pragma unroll
            for (int i = 0; i < 8; i++) {
                int j = cc * 64 + cg * 16 + i * 2 + (q >> 1);
                cold[i] = csrc[(size_t)(r0 + rowp) * 256 + j];
            }
            stageB(cc, 0, 0, sm, tid);
#pragma unroll 1
            for (int kt = 0; kt < 16; kt++) {
                asm volatile("cp.async.wait_group 0;");
                __syncthreads();
                if (kt < 15) stageB(cc, kt + 1, (kt + 1) & 1, sm, tid);
                uint4 ahi = *(const uint4*)(sm + OFF_A + ab * 65536 + ((rt * 16 + kt) * 128 + tx * 4) * 4);
                uint4 alo = *(const uint4*)(sm + OFF_A + ab * 65536 + 32768 + ((rt * 16 + kt) * 128 + tx * 4) * 4);
                const u64* Bh = (const u64*)(sm + OFF_B + (kt & 1) * 16384);
                const u64* Bl = Bh + 1024;
                u64 bh[8];
#pragma unroll
                for (int i = 0; i < 8; i++) bh[i] = Bh[(cg * 8 + i) * 32 + tx];
#pragma unroll
                for (int i = 0; i < 8; i++) mma16816(acc[i], ahi, bh[i]);
#pragma unroll
                for (int i = 0; i < 8; i++) mma16816(acc[i], ahi, Bl[(cg * 8 + i) * 32 + tx]);
#pragma unroll
                for (int i = 0; i < 8; i++) mma16816(acc[i], alo, bh[i]);
            }
            // epilogue: exchange gate halves, apply nonlinearity, update state
            const bool ev = !(q & 1);
#pragma unroll
            for (int i = 0; i < 8; i++) {
                float xg = ev ? acc[i][2] : acc[i][0];
                float yg = ev ? acc[i][3] : acc[i][1];
                float rx = __shfl_xor_sync(~0u, xg, 1);
                float ry = __shfl_xor_sync(~0u, yg, 1);
                float g0 = ev ? acc[i][0] : rx, g1 = ev ? acc[i][1] : ry;
                float g2 = ev ? rx : acc[i][2], g3 = ev ? ry : acc[i][3];
                int j = cc * 64 + cg * 16 + i * 2 + (q >> 1);
                int n4 = j << 2;
                g0 += sBias[n4]     + xv * sWih[n4 * 2]     + mv * sWih[n4 * 2 + 1];
                g1 += sBias[n4 + 1] + xv * sWih[n4 * 2 + 2] + mv * sWih[n4 * 2 + 3];
                g2 += sBias[n4 + 2] + xv * sWih[n4 * 2 + 4] + mv * sWih[n4 * 2 + 5];
                g3 += sBias[n4 + 3] + xv * sWih[n4 * 2 + 6] + mv * sWih[n4 * 2 + 7];
                float cn = sigm(g1) * cold[i] + sigm(g0) * tanh_f(g2);
                float h = sigm(g3) * tanh_f(cn);
                if (t < TSTEPS - 1) {
                    g_cstate[(size_t)(r0 + rowp) * 256 + j] = cn;
                    float hxo = __shfl_xor_sync(~0u, h, 2);   // partner has j^1
                    if (!(q >> 1)) {                           // j even owner
                        __nv_bfloat16 b0 = __float2bfloat16(h), b1v = __float2bfloat16(hxo);
                        __nv_bfloat162 hp; hp.x = b0; hp.y = b1v;
                        int kk = j & 15;
                        int lane2 = ((rowp & 7) << 2) + ((kk & 7) >> 1);
                        int reg2 = ((rowp & 15) >= 8) + ((kk >= 8) ? 2 : 0);
                        u32 off = OFF_A + nb * 65536 + ((rt * 16 + (j >> 4)) * 128 + lane2 * 4 + reg2) * 4;
                        *(u32*)(sm + off) = *(u32*)&hp;
                        *(u32*)(sm + off + 32768) =
                            pk2(h - __bfloat162float(b0), hxo - __bfloat162float(b1v));
                    }
                } else {
                    hd += h * sWlr[j];
                }
            }
        }
    }
    // combine head-dot partials: lanes q and q^2 share (row, cg)
    {
        float hs = hd + __shfl_xor_sync(~0u, hd, 2);
        if (!(q >> 1)) sHD4[rowp * 4 + cg] = hs;
    }
    __syncthreads();

    // ---- static MLP ----
    float* bufA = (float*)(sm + OFF_A);
    float* bufB = (float*)(sm + OFF_A + 65536);
    {
        float4* d = (float4*)bufA;
        const float4* s = (const float4*)(statf + (size_t)r0 * 256);
#pragma unroll
        for (int i = 0; i < 8; i++) d[tid + i * 512] = s[tid + i * 512];
    }
    __syncthreads();
    mlp_layer(bufA, bufB, W1, b1, sm, tid, tx, wid);
    mlp_layer(bufB, bufA, W2, b2p, sm, tid, tx, wid);
    mlp_layer(bufA, bufB, W3, b3, sm, tid, tx, wid);
    dot256_512(bufB, sWlr + 256, sSD, tid);
    __syncthreads();

    // ---- predicts + loss ----
    float lv = 0.f;
    if (tid < BM) {
        float p = sHD4[tid * 4] + sHD4[tid * 4 + 1] + sHD4[tid * 4 + 2] + sHD4[tid * 4 + 3]
                + sSD[tid] + blr[0];
        out[r0 + tid] = p;
        float tg = tgt[r0 + tid];
        lv = fmaxf(p, 0.f) - p * tg + log1pf(expf(-fabsf(p)));
    }
#pragma unroll
    for (int o = 16; o > 0; o >>= 1) lv += __shfl_down_sync(~0u, lv, o);
    if (tx == 0) sRed[wid] = lv;
    __syncthreads();
    if (tid == 0) {
        float s = 0.f;
#pragma unroll
        for (int i = 0; i < 16; i++) s += sRed[i];
        g_blockSums[blockIdx.x] = s;
    }
    __threadfence();
    if (tid == 0) {
        u32 n = atomicAdd(&g_ctr, 1u);
        sFlag[0] = (n == GRID - 1) ? 1 : 0;
    }
    __syncthreads();
    if (sFlag[0]) {
        float v = (tid < GRID) ? ((volatile float*)g_blockSums)[tid] : 0.f;
#pragma unroll
        for (int o = 16; o > 0; o >>= 1) v += __shfl_down_sync(~0u, v, o);
        if (tx == 0 && wid < 4) sRed[wid] = v;
        __syncthreads();
        if (tid == 0) {
            out[8192] = (sRed[0] + sRed[1] + sRed[2] + sRed[3]) * (1.f / 8192.f);
            g_ctr = 0;
        }
    }
}

extern "C" void kernel_launch(void* const* d_in, const int* in_sizes, int n_in,
                              void* d_out, int out_size) {
    cudaFuncSetAttribute(fused_kernel, cudaFuncAttributeMaxDynamicSharedMemorySize, SMEM_BYTES);
    prep_whh<<<512, 256>>>((const float*)d_in[7]);
    fused_kernel<<<GRID, NTHR, SMEM_BYTES>>>(
        (const float*)d_in[0], (const float*)d_in[1], (const float*)d_in[2],
        (const float*)d_in[3], (const float*)d_in[4], (const float*)d_in[5],
        (const float*)d_in[6], (const float*)d_in[7], (const float*)d_in[8],
        (const float*)d_in[9], (const float*)d_in[10], (const float*)d_in[11],
        (const float*)d_in[12], (const float*)d_in[13], (const float*)d_in[14],
        (const float*)d_in[15], (const float*)d_in[16], (const float*)d_in[17],
        (float*)d_out);
}

// round 16
// speedup vs baseline: 2.5502x; 1.2663x over previous
#include <cuda_runtime.h>
#include <cuda_bf16.h>

#define BM 64
#define GRID 128
#define NTHR 512
#define TSTEPS 24

typedef unsigned u32; typedef unsigned long long u64;

#define OFF_A    0          // A frags: [buf2][hi/lo][32KB] = 131072
#define OFF_B    131072     // B tiles: [buf2][32KB] = 65536 ; MLP tiles alias
#define OFF_BIAS 196608     // 4096 (reordered n=j*4+g)
#define OFF_WIH  200704     // 8192 (reordered)
#define OFF_TF   208896     // 6144
#define OFF_TM   215040     // 6144
#define OFF_WLR  221184     // 2048
#define OFF_HD8  223232     // 64*8 f32 = 2048
#define OFF_SD   225280     // 256
#define OFF_RED  225536     // 64
#define OFF_FLAG 225600     // 16
#define SMEM_BYTES 225616

__device__ float g_cstate[8192 * 256];
__device__ u32 g_bhi[131072];   // [kt16][ntpg64][lane32][ntodd2*reg2] u32
__device__ u32 g_blo[131072];
__device__ float g_blockSums[GRID];
__device__ u32 g_ctr;

__device__ __forceinline__ u32 smem_u32(const void* p) {
    u32 r; asm("{ .reg .u64 t; cvta.to.shared.u64 t, %1; cvt.u32.u64 %0, t; }" : "=r"(r) : "l"(p)); return r;
}
__device__ __forceinline__ float sigm(float x) { return 1.f / (1.f + __expf(-x)); }
__device__ __forceinline__ float tanh_f(float x) { return 1.f - 2.f / (__expf(2.f * x) + 1.f); }
__device__ __forceinline__ void cp16(void* d, const void* s) {
    asm volatile("cp.async.cg.shared.global [%0], [%1], 16;" :: "r"(smem_u32(d)), "l"(s));
}
__device__ __forceinline__ u32 pk2(float a, float b) {
    __nv_bfloat162 t = __floats2bfloat162_rn(a, b); return *(u32*)&t;
}
__device__ __forceinline__ void ffma2(u64& a, u64 x, u64 y) {
    asm volatile("fma.rn.f32x2 %0, %1, %2, %0;" : "+l"(a) : "l"(x), "l"(y));
}
__device__ __forceinline__ float2 up64(u64 v) { float2 r; asm("mov.b64 {%0,%1}, %2;" : "=f"(r.x), "=f"(r.y) : "l"(v)); return r; }

__device__ __forceinline__ void mma16816(float* d, const uint4& a, u32 b0, u32 b1) {
    asm volatile("mma.sync.aligned.m16n8k16.row.col.f32.bf16.bf16.f32 "
        "{%0,%1,%2,%3}, {%4,%5,%6,%7}, {%8,%9}, {%0,%1,%2,%3};"
        : "+f"(d[0]), "+f"(d[1]), "+f"(d[2]), "+f"(d[3])
        : "r"(a.x), "r"(a.y), "r"(a.z), "r"(a.w), "r"(b0), "r"(b1));
}

// Split W_hh into bf16 hi/lo B-fragments, nt-paired for LDS.128.
__global__ void prep_whh(const float* __restrict__ Whh) {
    int idx = blockIdx.x * 256 + threadIdx.x;     // 131072
    int n = idx >> 7, p = idx & 127, k = p * 2;
    int g = n & 3, j = n >> 2;
    const float* src = Whh + (size_t)((g << 8) + j) * 256 + k;
    float w0 = src[0], w1 = src[1];
    __nv_bfloat16 h0 = __float2bfloat16(w0), h1 = __float2bfloat16(w1);
    int kt = k >> 4, ntpg = n >> 4, ntodd = (n >> 3) & 1;
    int lane = (n & 7) * 4 + ((k & 7) >> 1);
    int reg = ((k & 15) >= 8);
    int pos = ((kt * 64 + ntpg) * 32 + lane) * 4 + ntodd * 2 + reg;
    __nv_bfloat162 hp; hp.x = h0; hp.y = h1;
    g_bhi[pos] = *(u32*)&hp;
    g_blo[pos] = pk2(w0 - __bfloat162float(h0), w1 - __bfloat162float(h1));
}

// stage 2 k-tiles (32KB): [ktl][hi 8K | lo 8K]
__device__ __forceinline__ void stageB2(int cc, int ktp, int buf, char* sm, int tid) {
#pragma unroll
    for (int i = 0; i < 4; i++) {
        const u32* src = (i & 1) ? g_blo : g_bhi;
        int kt = ktp * 2 + (i >> 1);
        src += (kt * 64 + cc * 16) * 128 + tid * 4;
        cp16(sm + OFF_B + buf * 32768 + i * 8192 + tid * 16, src);
    }
    asm volatile("cp.async.commit_group;");
}

// ---- MLP (SIMT f32x2), 64 rows, 512 threads ----
__device__ __forceinline__ void mlp_stage(const float* __restrict__ W, int cc, int kt,
                                          char* sm, int tid, int buf) {
    if (tid < 256) {
        int wr = tid >> 2, kpp = tid & 3;
        cp16(sm + OFF_B + (buf * 260 + kpp * 65 + wr) * 16,
             W + (size_t)(cc * 64 + wr) * 256 + (kt * 4 + kpp) * 4);
    }
    asm volatile("cp.async.commit_group;");
}
__device__ void mlp_layer(const float* in, float* outb, const float* __restrict__ W,
                          const float* __restrict__ bias, char* sm, int tid, int tx, int wid) {
    const ulonglong2* Au = (const ulonglong2*)in;
    const int rb = (wid >> 1) * 8, cl = (wid & 1) * 32 + tx;
#pragma unroll 1
    for (int cc = 0; cc < 4; cc++) {
        u64 acc[8];
#pragma unroll
        for (int v = 0; v < 8; v++) acc[v] = 0ull;
        mlp_stage(W, cc, 0, sm, tid, 0);
#pragma unroll 1
        for (int kt = 0; kt < 16; kt++) {
            asm volatile("cp.async.wait_group 0;");
            __syncthreads();
            if (kt < 15) mlp_stage(W, cc, kt + 1, sm, tid, (kt + 1) & 1);
            const ulonglong2* Tt = (const ulonglong2*)(sm + OFF_B) + (kt & 1) * 260;
#pragma unroll
            for (int kpp = 0; kpp < 4; kpp++) {
                ulonglong2 b = Tt[kpp * 65 + cl];
#pragma unroll
                for (int v = 0; v < 8; v++) {
                    ulonglong2 a = Au[(rb + v) * 64 + kt * 4 + kpp];
                    ffma2(acc[v], a.x, b.x); ffma2(acc[v], a.y, b.y);
                }
            }
        }
        __syncthreads();
        int n = cc * 64 + cl; float bb = bias[n];
#pragma unroll
        for (int v = 0; v < 8; v++) {
            float2 p = up64(acc[v]);
            outb[(rb + v) * 256 + n] = fmaxf(p.x + p.y + bb, 0.f);
        }
        __syncthreads();
    }
}
__device__ __forceinline__ void dot256_512(const float* buf, const float* w, float* outv, int tid) {
    int r = tid >> 3, q = tid & 7;
    const float4* hv = (const float4*)(buf + r * 256 + q * 32);
    const float4* wv = (const float4*)(w + q * 32);
    float s = 0.f;
#pragma unroll
    for (int i = 0; i < 8; i++) {
        float4 a = hv[i], b = wv[i];
        s += a.x * b.x + a.y * b.y + a.z * b.z + a.w * b.w;
    }
    s += __shfl_xor_sync(~0u, s, 1);
    s += __shfl_xor_sync(~0u, s, 2);
    s += __shfl_xor_sync(~0u, s, 4);
    if (q == 0) outv[r] = s;
}

__global__ void __launch_bounds__(NTHR, 1)
fused_kernel(const float* __restrict__ statf, const float* __restrict__ tf,
             const float* __restrict__ tm, const float* __restrict__ tgt,
             const float* __restrict__ h0, const float* __restrict__ c0,
             const float* __restrict__ Wih, const float* __restrict__ Whh,
             const float* __restrict__ bih, const float* __restrict__ bhh,
             const float* __restrict__ W1, const float* __restrict__ b1,
             const float* __restrict__ W2, const float* __restrict__ b2p,
             const float* __restrict__ W3, const float* __restrict__ b3,
             const float* __restrict__ Wlr, const float* __restrict__ blr,
             float* __restrict__ out) {
    extern __shared__ __align__(1024) char sm[];
    const int tid = threadIdx.x, tx = tid & 31, wid = tid >> 5;
    const int rg = wid >> 3, ng = wid & 7, q = tx & 3;
    const int r0 = blockIdx.x * BM;
    const int rowp0 = rg * 32 + (tx >> 2) + ((q & 1) << 3);  // rt2=0 epilogue row

    float* sBias = (float*)(sm + OFF_BIAS);
    float* sWih = (float*)(sm + OFF_WIH);
    float* sTF = (float*)(sm + OFF_TF);
    float* sTM = (float*)(sm + OFF_TM);
    float* sWlr = (float*)(sm + OFF_WLR);
    float* sHD8 = (float*)(sm + OFF_HD8);
    float* sSD = (float*)(sm + OFF_SD);
    float* sRed = (float*)(sm + OFF_RED);
    int* sFlag = (int*)(sm + OFF_FLAG);

#pragma unroll
    for (int i = 0; i < 2; i++) {
        int n = tid + i * 512, g = n & 3, j = n >> 2;
        sBias[n] = bih[(g << 8) + j] + bhh[(g << 8) + j];
    }
#pragma unroll
    for (int i = 0; i < 4; i++) {
        int m = tid + i * 512, n = m >> 1, c = m & 1, g = n & 3, j = n >> 2;
        sWih[m] = Wih[(size_t)((g << 8) + j) * 2 + c];
    }
#pragma unroll
    for (int i = 0; i < 3; i++) {
        int k = tid + i * 512;
        sTF[k] = tf[(size_t)r0 * 24 + k];
        sTM[k] = tm[(size_t)r0 * 24 + k];
    }
    if (tid < 512) sWlr[tid] = Wlr[tid];
    // A-frag init from h0 (buf 0)
#pragma unroll
    for (int i = 0; i < 16; i++) {
        int idx = tid + i * 512;
        int r = idx >> 7, p = idx & 127, k = p * 2;
        float2 v = *(const float2*)(h0 + (size_t)(r0 + r) * 256 + k);
        __nv_bfloat16 bx = __float2bfloat16(v.x), by = __float2bfloat16(v.y);
        __nv_bfloat162 hp; hp.x = bx; hp.y = by;
        int rr = r & 15, kk = k & 15;
        int lane = (rr & 7) * 4 + ((kk & 7) >> 1);
        int reg = (rr >= 8) + ((kk >= 8) ? 2 : 0);
        u32 off = OFF_A + (((r >> 4) * 16 + (k >> 4)) * 128 + lane * 4 + reg) * 4;
        *(u32*)(sm + off) = *(u32*)&hp;
        *(u32*)(sm + off + 32768) = pk2(v.x - __bfloat162float(bx), v.y - __bfloat162float(by));
    }
    __syncthreads();

    // prologue: stage (cc=0, ktp=0) into buf 0
    stageB2(0, 0, 0, sm, tid);
    int ncc = 0, nktp = 1, cbuf = 0;
    float hd0 = 0.f, hd1 = 0.f;

#pragma unroll 1
    for (int t = 0; t < TSTEPS; t++) {
        const int ab = t & 1, nb = ab ^ 1;
        const float* csrc = t ? g_cstate : c0;
        const float xv0 = sTF[rowp0 * 24 + t], mv0 = sTM[rowp0 * 24 + t];
        const float xv1 = sTF[(rowp0 + 16) * 24 + t], mv1 = sTM[(rowp0 + 16) * 24 + t];
#pragma unroll 1
        for (int cc = 0; cc < 4; cc++) {
            float acc[2][4][4];
#pragma unroll
            for (int a = 0; a < 2; a++)
#pragma unroll
                for (int b = 0; b < 4; b++)
#pragma unroll
                    for (int d = 0; d < 4; d++) acc[a][b][d] = 0.f;
            float cold[2][4];
#pragma unroll
            for (int rt2 = 0; rt2 < 2; rt2++)
#pragma unroll
                for (int nt = 0; nt < 4; nt++) {
                    int j = cc * 64 + (ng * 4 + nt) * 2 + (q >> 1);
                    cold[rt2][nt] = csrc[(size_t)(r0 + rowp0 + rt2 * 16) * 256 + j];
                }
#pragma unroll 1
            for (int ktp = 0; ktp < 8; ktp++) {
                asm volatile("cp.async.wait_group 0;");
                __syncthreads();
                bool last = (t == TSTEPS - 1) && (cc == 3) && (ktp == 7);
                if (!last) {
                    stageB2(ncc, nktp, cbuf ^ 1, sm, tid);
                    if (++nktp == 8) { nktp = 0; ncc = (ncc + 1) & 3; }
                }
#pragma unroll
                for (int ktl = 0; ktl < 2; ktl++) {
                    int kt = ktp * 2 + ktl;
                    uint4 ahi[2], alo[2];
#pragma unroll
                    for (int rt2 = 0; rt2 < 2; rt2++) {
                        u32 ao = OFF_A + ab * 65536 + ((rg * 2 + rt2) * 16 + kt) * 512 + tx * 16;
                        ahi[rt2] = *(const uint4*)(sm + ao);
                        alo[rt2] = *(const uint4*)(sm + ao + 32768);
                    }
                    u32 bo = OFF_B + cbuf * 32768 + ktl * 16384 + ng * 1024 + tx * 16;
                    uint4 bh0 = *(const uint4*)(sm + bo);
                    uint4 bh1 = *(const uint4*)(sm + bo + 512);
                    uint4 bl0 = *(const uint4*)(sm + bo + 8192);
                    uint4 bl1 = *(const uint4*)(sm + bo + 8704);
                    u32 bhx[4][2] = {{bh0.x,bh0.y},{bh0.z,bh0.w},{bh1.x,bh1.y},{bh1.z,bh1.w}};
                    u32 blx[4][2] = {{bl0.x,bl0.y},{bl0.z,bl0.w},{bl1.x,bl1.y},{bl1.z,bl1.w}};
#pragma unroll
                    for (int nt = 0; nt < 4; nt++)
#pragma unroll
                        for (int rt2 = 0; rt2 < 2; rt2++) {
                            mma16816(acc[rt2][nt], ahi[rt2], bhx[nt][0], bhx[nt][1]);
                            mma16816(acc[rt2][nt], ahi[rt2], blx[nt][0], blx[nt][1]);
                            mma16816(acc[rt2][nt], alo[rt2], bhx[nt][0], bhx[nt][1]);
                        }
                }
                cbuf ^= 1;
            }
            // epilogue
            const bool ev = !(q & 1);
#pragma unroll
            for (int rt2 = 0; rt2 < 2; rt2++) {
                const float xv = rt2 ? xv1 : xv0, mv = rt2 ? mv1 : mv0;
                const int rowp = rowp0 + rt2 * 16;
#pragma unroll
                for (int nt = 0; nt < 4; nt++) {
                    float* d = acc[rt2][nt];
                    float xg = ev ? d[2] : d[0];
                    float yg = ev ? d[3] : d[1];
                    float rx = __shfl_xor_sync(~0u, xg, 1);
                    float ry = __shfl_xor_sync(~0u, yg, 1);
                    float g0 = ev ? d[0] : rx, g1 = ev ? d[1] : ry;
                    float g2 = ev ? rx : d[2], g3 = ev ? ry : d[3];
                    int j = cc * 64 + (ng * 4 + nt) * 2 + (q >> 1);
                    int n4 = j << 2;
                    g0 += sBias[n4]     + xv * sWih[n4 * 2]     + mv * sWih[n4 * 2 + 1];
                    g1 += sBias[n4 + 1] + xv * sWih[n4 * 2 + 2] + mv * sWih[n4 * 2 + 3];
                    g2 += sBias[n4 + 2] + xv * sWih[n4 * 2 + 4] + mv * sWih[n4 * 2 + 5];
                    g3 += sBias[n4 + 3] + xv * sWih[n4 * 2 + 6] + mv * sWih[n4 * 2 + 7];
                    float cn = sigm(g1) * cold[rt2][nt] + sigm(g0) * tanh_f(g2);
                    float h = sigm(g3) * tanh_f(cn);
                    if (t < TSTEPS - 1) {
                        g_cstate[(size_t)(r0 + rowp) * 256 + j] = cn;
                        float hxo = __shfl_xor_sync(~0u, h, 2);
                        if (!(q >> 1)) {
                            __nv_bfloat16 b0 = __float2bfloat16(h), b1v = __float2bfloat16(hxo);
                            __nv_bfloat162 hp; hp.x = b0; hp.y = b1v;
                            int kk = j & 15;
                            int lane2 = ((rowp & 7) << 2) + ((kk & 7) >> 1);
                            int reg2 = ((rowp & 15) >= 8) + ((kk >= 8) ? 2 : 0);
                            u32 off = OFF_A + nb * 65536 +
                                      (((rowp >> 4) * 16 + (j >> 4)) * 128 + lane2 * 4 + reg2) * 4;
                            *(u32*)(sm + off) = *(u32*)&hp;
                            *(u32*)(sm + off + 32768) =
                                pk2(h - __bfloat162float(b0), hxo - __bfloat162float(b1v));
                        }
                    } else {
                        if (rt2) hd1 += h * sWlr[j]; else hd0 += h * sWlr[j];
                    }
                }
            }
        }
    }
    // head-dot partials: combine q<->q^2 (j pairs), write per (row, ng)
    {
        float hs0 = hd0 + __shfl_xor_sync(~0u, hd0, 2);
        float hs1 = hd1 + __shfl_xor_sync(~0u, hd1, 2);
        if (q < 2) {
            sHD8[rowp0 * 8 + ng] = hs0;
            sHD8[(rowp0 + 16) * 8 + ng] = hs1;
        }
    }
    __syncthreads();

    // ---- static MLP ----
    float* bufA = (float*)(sm + OFF_A);
    float* bufB = (float*)(sm + OFF_A + 65536);
    {
        float4* d = (float4*)bufA;
        const float4* s = (const float4*)(statf + (size_t)r0 * 256);
#pragma unroll
        for (int i = 0; i < 8; i++) d[tid + i * 512] = s[tid + i * 512];
    }
    __syncthreads();
    mlp_layer(bufA, bufB, W1, b1, sm, tid, tx, wid);
    mlp_layer(bufB, bufA, W2, b2p, sm, tid, tx, wid);
    mlp_layer(bufA, bufB, W3, b3, sm, tid, tx, wid);
    dot256_512(bufB, sWlr + 256, sSD, tid);
    __syncthreads();

    // ---- predicts + loss ----
    float lv = 0.f;
    if (tid < BM) {
        float p = blr[0] + sSD[tid];
#pragma unroll
        for (int i = 0; i < 8; i++) p += sHD8[tid * 8 + i];
        out[r0 + tid] = p;
        float tg = tgt[r0 + tid];
        lv = fmaxf(p, 0.f) - p * tg + log1pf(expf(-fabsf(p)));
    }
#pragma unroll
    for (int o = 16; o > 0; o >>= 1) lv += __shfl_down_sync(~0u, lv, o);
    if (tx == 0) sRed[wid] = lv;
    __syncthreads();
    if (tid == 0) {
        float s = 0.f;
#pragma unroll
        for (int i = 0; i < 16; i++) s += sRed[i];
        g_blockSums[blockIdx.x] = s;
    }
    __threadfence();
    if (tid == 0) {
        u32 n = atomicAdd(&g_ctr, 1u);
        sFlag[0] = (n == GRID - 1) ? 1 : 0;
    }
    __syncthreads();
    if (sFlag[0]) {
        float v = (tid < GRID) ? ((volatile float*)g_blockSums)[tid] : 0.f;
#pragma unroll
        for (int o = 16; o > 0; o >>= 1) v += __shfl_down_sync(~0u, v, o);
        if (tx == 0 && wid < 4) sRed[wid] = v;
        __syncthreads();
        if (tid == 0) {
            out[8192] = (sRed[0] + sRed[1] + sRed[2] + sRed[3]) * (1.f / 8192.f);
            g_ctr = 0;
        }
    }
}

extern "C" void kernel_launch(void* const* d_in, const int* in_sizes, int n_in,
                              void* d_out, int out_size) {
    cudaFuncSetAttribute(fused_kernel, cudaFuncAttributeMaxDynamicSharedMemorySize, SMEM_BYTES);
    prep_whh<<<512, 256>>>((const float*)d_in[7]);
    fused_kernel<<<GRID, NTHR, SMEM_BYTES>>>(
        (const float*)d_in[0], (const float*)d_in[1], (const float*)d_in[2],
        (const float*)d_in[3], (const float*)d_in[4], (const float*)d_in[5],
        (const float*)d_in[6], (const float*)d_in[7], (const float*)d_in[8],
        (const float*)d_in[9], (const float*)d_in[10], (const float*)d_in[11],
        (const float*)d_in[12], (const float*)d_in[13], (const float*)d_in[14],
        (const float*)d_in[15], (const float*)d_in[16], (const float*)d_in[17],
        (float*)d_out);
}